// round 15
// baseline (speedup 1.0000x reference)
#include <cuda_runtime.h>
#include <cuda_bf16.h>
#include <math.h>

#define BB 16
#define CCH 256
#define TT 576
#define NH 8
#define QSCALE 0.17677669529663687f
#define GN_EPS 1e-5f
#define ZS 17
#define JPS 17

__device__ float g_qt[BB * NH * TT * 32];
__device__ uint2 g_k[BB * NH * TT * 16];      // (hi,lo) bf16x2 d-pairs, [bn][t][dp]
__device__ uint2 g_v[BB * NH * 32 * 288];     // (hi,lo) bf16x2 j-pairs, [bn][d][jp]
__device__ uint2 g_wq[768 * 128];             // pre-split qkv_w, pairs along c
__device__ uint2 g_wf[256 * 128];             // pre-split fc_w, pairs along c
__device__ float g_E[BB * NH * TT * 48];
__device__ float g_P[48 * 256];
__device__ float g_R[NH * 47 * 32];
__device__ float g_att[BB * TT * CCH];
__device__ float g_y[BB * CCH * TT];
__device__ float g_mu[BB * 16];
__device__ float g_rstd[BB * 16];

__device__ __forceinline__ unsigned pack_bf16(float x, float y) {
    __nv_bfloat162 t = __floats2bfloat162_rn(x, y);
    return *reinterpret_cast<unsigned*>(&t);
}
__device__ __forceinline__ void split_pair(float x, float y, unsigned& hi, unsigned& lo) {
    float xh = __bfloat162float(__float2bfloat16_rn(x));
    float yh = __bfloat162float(__float2bfloat16_rn(y));
    hi = pack_bf16(xh, yh);
    lo = pack_bf16(x - xh, y - yh);
}
__device__ __forceinline__ void mma_bf16(float* d, const unsigned* a, const unsigned* b) {
    asm volatile("mma.sync.aligned.m16n8k16.row.col.f32.bf16.bf16.f32 "
                 "{%0,%1,%2,%3},{%4,%5,%6,%7},{%8,%9},{%0,%1,%2,%3};"
                 : "+f"(d[0]), "+f"(d[1]), "+f"(d[2]), "+f"(d[3])
                 : "r"(a[0]), "r"(a[1]), "r"(a[2]), "r"(a[3]), "r"(b[0]), "r"(b[1]));
}

// ---------- k0: P, R tables + weight pre-splits ----------
__global__ void k0_prep(const float* __restrict__ rh_v, const float* __restrict__ rw_v,
                        const float* __restrict__ rh_k, const float* __restrict__ rw_k,
                        const float* __restrict__ qkv_w, const float* __restrict__ fc_w) {
    int bx = blockIdx.x, tid = threadIdx.x;
    if (bx < 48) {
        int idx = bx * 256 + tid;
        int m = idx >> 8, rest = idx & 255;
        g_P[idx] = (m > 0) ? (rh_v[(m - 1) * 256 + rest] + rw_v[(m - 1) * 256 + rest]) : 0.f;
    } else if (bx < 95) {
        int l = bx - 48;
        int n = tid >> 5, d = tid & 31;
        g_R[(n * 47 + l) * 32 + d] = rh_k[(l * 8 + n) * 32 + d] + rw_k[(l * 8 + n) * 32 + d];
    } else if (bx < 479) {
        int idx = (bx - 95) * 256 + tid;      // 384 blocks: 768*128 pairs
        int o = idx >> 7, cp = idx & 127;
        unsigned hi, lo;
        split_pair(qkv_w[o * 256 + 2 * cp], qkv_w[o * 256 + 2 * cp + 1], hi, lo);
        g_wq[idx] = make_uint2(hi, lo);
    } else {
        int idx = (bx - 479) * 256 + tid;     // 128 blocks: 256*128 pairs
        int o = idx >> 7, cp = idx & 127;
        unsigned hi, lo;
        split_pair(fc_w[o * 256 + 2 * cp], fc_w[o * 256 + 2 * cp + 1], hi, lo);
        g_wf[idx] = make_uint2(hi, lo);
    }
}

// ---------- k1: qkv GEMM via bf16-split mma; epilogue emits q f32 / k,v split ----------
__global__ __launch_bounds__(256) void k1_qkv(const float* __restrict__ x,
                                              const float* __restrict__ bias) {
    __shared__ uint2 Xs[32][66];    // x pairs: [cp][t]
    __shared__ uint2 Ws[64][33];    // w pairs: [o][cp]
    __shared__ float Ts[64][68];    // output staging [t][o]
    int b = blockIdx.z, o0 = blockIdx.y * 64, i0 = blockIdx.x * 64;
    int tid = threadIdx.x, warp = tid >> 5, lane = tid & 31;
    int qr = lane >> 2, qc = lane & 3;
    int og = (warp >> 1) * 16;
    int t0w = (warp & 1) * 32;
    const float* xb = x + (size_t)b * CCH * TT;
    float acc[4][4] = {};

    for (int c0 = 0; c0 < 256; c0 += 64) {
#pragma unroll
        for (int rr = 0; rr < 8; rr++) {
            int idx = tid + 256 * rr;
            int cp = idx >> 6, tc = idx & 63;
            float x0 = xb[(c0 + 2 * cp) * TT + i0 + tc];
            float x1 = xb[(c0 + 2 * cp + 1) * TT + i0 + tc];
            unsigned hi, lo; split_pair(x0, x1, hi, lo);
            Xs[cp][tc] = make_uint2(hi, lo);
        }
#pragma unroll
        for (int rr = 0; rr < 8; rr++) {
            int idx = tid + 256 * rr;
            int o = idx >> 5, cpl = idx & 31;
            Ws[o][cpl] = g_wq[(o0 + o) * 128 + (c0 >> 1) + cpl];
        }
        __syncthreads();
#pragma unroll
        for (int ks = 0; ks < 4; ks++) {
            uint2 a0 = Ws[og + qr][ks * 8 + qc];
            uint2 a1 = Ws[og + qr + 8][ks * 8 + qc];
            uint2 a2 = Ws[og + qr][ks * 8 + qc + 4];
            uint2 a3 = Ws[og + qr + 8][ks * 8 + qc + 4];
            unsigned ahf[4] = {a0.x, a1.x, a2.x, a3.x};
            unsigned alf[4] = {a0.y, a1.y, a2.y, a3.y};
#pragma unroll
            for (int nf = 0; nf < 4; nf++) {
                int tt = t0w + 8 * nf + qr;
                uint2 b0 = Xs[ks * 8 + qc][tt];
                uint2 b1 = Xs[ks * 8 + qc + 4][tt];
                unsigned bh[2] = {b0.x, b1.x};
                unsigned bl[2] = {b0.y, b1.y};
                mma_bf16(acc[nf], ahf, bh);
                mma_bf16(acc[nf], ahf, bl);
                mma_bf16(acc[nf], alf, bh);
            }
        }
        __syncthreads();
    }
#pragma unroll
    for (int nf = 0; nf < 4; nf++)
#pragma unroll
        for (int r = 0; r < 4; r++) {
            int ol = og + qr + (r >> 1) * 8;
            int tl = t0w + 8 * nf + 2 * qc + (r & 1);
            Ts[tl][ol] = acc[nf][r] + bias[o0 + ol];
        }
    __syncthreads();
    int sec = o0 >> 8;                  // 0=q, 1=k, 2=v
    int h0 = (o0 & 255) >> 5;
    if (sec == 0) {
        int tl_ = tid >> 2, quad = tid & 3;
#pragma unroll
        for (int k4 = 0; k4 < 4; k4++) {
            int ol = quad * 16 + k4 * 4;
            int head = h0 + (ol >> 5);
            int d = ol & 31;
            float4 v = *(const float4*)&Ts[tl_][ol];
            *(float4*)&g_qt[(((size_t)b * NH + head) * TT + i0 + tl_) * 32 + d] = v;
        }
    } else if (sec == 1) {
#pragma unroll
        for (int wI = 0; wI < 8; wI++) {
            int idx = tid + 256 * wI;
            int hh = idx >> 10, tl = (idx >> 4) & 63, dp = idx & 15;
            float xv = Ts[tl][hh * 32 + 2 * dp], yv = Ts[tl][hh * 32 + 2 * dp + 1];
            unsigned hi, lo; split_pair(xv, yv, hi, lo);
            size_t a = (((size_t)b * NH + h0 + hh) * TT + i0 + tl) * 16 + dp;
            g_k[a] = make_uint2(hi, lo);
        }
    } else {
#pragma unroll
        for (int wI = 0; wI < 8; wI++) {
            int idx = tid + 256 * wI;
            int hh = idx >> 10, dd = (idx >> 5) & 31, jp = idx & 31;
            float xv = Ts[2 * jp][hh * 32 + dd], yv = Ts[2 * jp + 1][hh * 32 + dd];
            unsigned hi, lo; split_pair(xv, yv, hi, lo);
            size_t a = (((size_t)b * NH + h0 + hh) * 32 + dd) * 288 + (i0 >> 1) + jp;
            g_v[a] = make_uint2(hi, lo);
        }
    }
}

// ---------- kE ----------
__global__ __launch_bounds__(256) void kE_gemm() {
    __shared__ float Qs[64][36];
    __shared__ float Rs[48][36];
    int bn = blockIdx.y;
    int iu0 = blockIdx.x * 64;
    int n = bn & 7;
    int tid = threadIdx.x;
    const float* qsrc = g_qt + ((size_t)bn * TT + iu0) * 32;
    for (int idx = tid; idx < 64 * 32; idx += 256) Qs[idx >> 5][idx & 31] = qsrc[idx];
    for (int idx = tid; idx < 48 * 32; idx += 256) {
        int r = idx >> 5, d = idx & 31;
        Rs[r][d] = (r < 47) ? g_R[(n * 47 + r) * 32 + d] : 0.f;
    }
    __syncthreads();
    int tl = tid & 15, tiu = tid >> 4;
    float acc[4][3] = {};
#pragma unroll
    for (int d4 = 0; d4 < 8; d4++) {
        float4 q4[4], r4[3];
#pragma unroll
        for (int r = 0; r < 4; r++) q4[r] = *(const float4*)&Qs[tiu * 4 + r][d4 * 4];
#pragma unroll
        for (int j = 0; j < 3; j++) r4[j] = *(const float4*)&Rs[tl * 3 + j][d4 * 4];
#pragma unroll
        for (int r = 0; r < 4; r++)
#pragma unroll
            for (int j = 0; j < 3; j++)
                acc[r][j] += q4[r].x * r4[j].x + q4[r].y * r4[j].y +
                             q4[r].z * r4[j].z + q4[r].w * r4[j].w;
    }
    float* ep = g_E + ((size_t)bn * TT + iu0) * 48;
#pragma unroll
    for (int r = 0; r < 4; r++)
#pragma unroll
        for (int j = 0; j < 3; j++)
            ep[(tiu * 4 + r) * 48 + tl * 3 + j] = acc[r][j];
}

// ---------- k3: fused attention; SINGLE CHANGE THIS ROUND: 3 CTAs/SM (reg cap 85) ----------
__global__ __launch_bounds__(256, 3) void k3_attn() {
    extern __shared__ float sm[];
    float* z_s  = sm;                          // [8][32][ZS]  4352 floats
    uint2* za   = (uint2*)(sm + 4352);         // [8][16][JPS] 2176 uint2
    float* A_s  = sm + 4352 + 4352;            // [8][16][25]  3200 floats
    float* bd_s = A_s + 3200;                  // [8][16][24]  3072 floats
    uint2* Ssm  = (uint2*)(bd_s + 3072);       // [3][2][3][32] 576 uint2
    int b = blockIdx.y, i0 = blockIdx.x * 16;
    int tid = threadIdx.x, warp = tid >> 5, lane = tid & 31;
    int n = warp, bn = b * NH + n;
    int qr = lane >> 2, qc = lane & 3;

    for (int idx = tid; idx < 8 * 16 * 24; idx += 256) {
        int nn = idx / 384, r = idx % 384, ii = r / 24, c = r % 24;
        int ig = i0 + ii;
        int diff = c - ig;
        int fl = (diff >= 0) ? 0 : -((-diff + 47) / 48);
        int l = diff - 48 * fl;
        int iu = 12 + ig + fl;
        bd_s[idx] = l ? g_E[(((size_t)b * NH + nn) * TT + iu) * 48 + (l - 1)] : 0.f;
    }
    for (int idx = tid; idx < 576; idx += 256) {
        int l = idx & 31, rest = idx >> 5;
        int nf = rest % 3, kkc = rest / 3;
        int kk = kkc & 1, jcls = kkc >> 1;
        int qr_ = l >> 2, qc_ = l & 3;
        int jm0 = (8 * jcls + 16 * kk + 2 * qc_) % 24;
        int jm1 = (jm0 + 1) % 24;
        int jm8 = (jm0 + 8) % 24;
        int jm9 = (jm8 + 1) % 24;
        int cg = 8 * nf + qr_;
        Ssm[idx] = make_uint2(pack_bf16(jm0 == cg ? 1.f : 0.f, jm1 == cg ? 1.f : 0.f),
                              pack_bf16(jm8 == cg ? 1.f : 0.f, jm9 == cg ? 1.f : 0.f));
    }

    unsigned qh[2][4], ql[2][4];
#pragma unroll
    for (int kk = 0; kk < 2; kk++)
#pragma unroll
        for (int r = 0; r < 4; r++) {
            int row = i0 + qr + (r & 1) * 8;
            int col = 16 * kk + 2 * qc + (r >> 1) * 8;
            float2 v = *(const float2*)&g_qt[((size_t)bn * TT + row) * 32 + col];
            split_pair(v.x, v.y, qh[kk][r], ql[kk][r]);
        }

    const uint2* kb = g_k + (size_t)bn * TT * 16;
    const uint2* vb = g_v + (size_t)bn * 32 * 288;

    float oacc[4][4];
#pragma unroll
    for (int df = 0; df < 4; df++)
#pragma unroll
        for (int r = 0; r < 4; r++) oacc[df][r] = 0.f;
    float cA[3][4];
#pragma unroll
    for (int nf = 0; nf < 3; nf++)
#pragma unroll
        for (int r = 0; r < 4; r++) cA[nf][r] = 0.f;
    __syncthreads();

    for (int jt = 0; jt < TT; jt += 32) {
        int jtc = jt % 24;
        int jcls = (jt >> 5) % 3;
#pragma unroll
        for (int jf = 0; jf < 4; jf++) {
            float z[4] = {0.f, 0.f, 0.f, 0.f};
#pragma unroll
            for (int kk = 0; kk < 2; kk++) {
                unsigned base = (unsigned)(jt + 8 * jf + qr) * 16u + qc + 8 * kk;
                uint2 w0 = kb[base], w1 = kb[base + 4];
                unsigned bh[2] = {w0.x, w1.x};
                unsigned bl[2] = {w0.y, w1.y};
                mma_bf16(z, qh[kk], bh);
                mma_bf16(z, qh[kk], bl);
                mma_bf16(z, ql[kk], bh);
            }
            int jl0 = 8 * jf + 2 * qc;
            int c0 = jtc + jl0;     if (c0 >= 24) c0 -= 24; if (c0 >= 24) c0 -= 24;
            int c1 = jtc + jl0 + 1; if (c1 >= 24) c1 -= 24; if (c1 >= 24) c1 -= 24;
            z[0] += bd_s[(n * 16 + qr) * 24 + c0];
            z[1] += bd_s[(n * 16 + qr) * 24 + c1];
            z[2] += bd_s[(n * 16 + qr + 8) * 24 + c0];
            z[3] += bd_s[(n * 16 + qr + 8) * 24 + c1];
            z_s[(n * 32 + jl0) * ZS + qr]         = z[0];
            z_s[(n * 32 + jl0 + 1) * ZS + qr]     = z[1];
            z_s[(n * 32 + jl0) * ZS + qr + 8]     = z[2];
            z_s[(n * 32 + jl0 + 1) * ZS + qr + 8] = z[3];
        }
        __syncthreads();
        {
            int jp = tid & 15, i = tid >> 4;
            int j0 = 2 * jp;
            float z0[8], z1[8];
#pragma unroll
            for (int m = 0; m < 8; m++) {
                z0[m] = z_s[(m * 32 + j0) * ZS + i] * QSCALE;
                z1[m] = z_s[(m * 32 + j0 + 1) * ZS + i] * QSCALE;
            }
            float mx0 = z0[0], mx1 = z1[0];
#pragma unroll
            for (int m = 1; m < 8; m++) { mx0 = fmaxf(mx0, z0[m]); mx1 = fmaxf(mx1, z1[m]); }
            float s0 = 0.f, s1 = 0.f;
#pragma unroll
            for (int m = 0; m < 8; m++) {
                z0[m] = __expf(z0[m] - mx0); s0 += z0[m];
                z1[m] = __expf(z1[m] - mx1); s1 += z1[m];
            }
            float inv0 = 1.f / s0, inv1 = 1.f / s1;
#pragma unroll
            for (int m = 0; m < 8; m++) {
                unsigned hi, lo;
                split_pair(z0[m] * inv0, z1[m] * inv1, hi, lo);
                za[(m * 16 + i) * JPS + jp] = make_uint2(hi, lo);
            }
        }
        __syncthreads();
        unsigned ah[2][4], al[2][4];
#pragma unroll
        for (int kk = 0; kk < 2; kk++)
#pragma unroll
            for (int r = 0; r < 4; r++) {
                int jp = 8 * kk + qc + (r >> 1) * 4;
                int ir = qr + (r & 1) * 8;
                uint2 wv = za[(n * 16 + ir) * JPS + jp];
                ah[kk][r] = wv.x; al[kk][r] = wv.y;
            }
#pragma unroll
        for (int kk = 0; kk < 2; kk++) {
#pragma unroll
            for (int nf = 0; nf < 3; nf++) {
                uint2 sv = Ssm[((jcls * 2 + kk) * 3 + nf) * 32 + lane];
                unsigned sb[2] = {sv.x, sv.y};
                mma_bf16(cA[nf], ah[kk], sb);
                mma_bf16(cA[nf], al[kk], sb);
            }
        }
#pragma unroll
        for (int df = 0; df < 4; df++) {
#pragma unroll
            for (int kk = 0; kk < 2; kk++) {
                unsigned base = (unsigned)(qr + 8 * df) * 288u + (jt >> 1) + qc + 8 * kk;
                uint2 w0 = vb[base], w1 = vb[base + 4];
                unsigned bh[2] = {w0.x, w1.x};
                unsigned bl[2] = {w0.y, w1.y};
                mma_bf16(oacc[df], ah[kk], bh);
                mma_bf16(oacc[df], ah[kk], bl);
                mma_bf16(oacc[df], al[kk], bh);
            }
        }
    }
#pragma unroll
    for (int nf = 0; nf < 3; nf++) {
        int cg = 8 * nf + 2 * qc;
        A_s[(n * 16 + qr) * 25 + cg]         = cA[nf][0];
        A_s[(n * 16 + qr) * 25 + cg + 1]     = cA[nf][1];
        A_s[(n * 16 + qr + 8) * 25 + cg]     = cA[nf][2];
        A_s[(n * 16 + qr + 8) * 25 + cg + 1] = cA[nf][3];
    }
    __syncwarp();
#pragma unroll
    for (int df = 0; df < 4; df++)
#pragma unroll
        for (int r = 0; r < 4; r++) {
            int ii = qr + (r >> 1) * 8;
            int d  = 8 * df + 2 * qc + (r & 1);
            int ig = i0 + ii;
            float o2 = 0.f;
#pragma unroll
            for (int c = 0; c < 24; c++) {
                int m = (c - ig) % 48; if (m < 0) m += 48;
                o2 += A_s[(n * 16 + ii) * 25 + c] * g_P[m * 256 + n * 32 + d];
            }
            g_att[((size_t)b * TT + ig) * CCH + n * 32 + d] = oacc[df][r] + o2;
        }
}

// ---------- k4: fc GEMM via bf16-split mma + residual ----------
__global__ __launch_bounds__(256) void k4_fc(const float* __restrict__ x,
                                             const float* __restrict__ bias) {
    __shared__ uint2 Xs[32][67];    // att pairs: [cp][t]
    __shared__ uint2 Ws[64][33];    // w pairs: [o][cp]
    int b = blockIdx.z, o0 = blockIdx.y * 64, i0 = blockIdx.x * 64;
    int tid = threadIdx.x, warp = tid >> 5, lane = tid & 31;
    int qr = lane >> 2, qc = lane & 3;
    int og = (warp >> 1) * 16;
    int t0w = (warp & 1) * 32;
    const float* att = g_att + (size_t)b * TT * CCH;
    float acc[4][4] = {};

    for (int c0 = 0; c0 < 256; c0 += 64) {
#pragma unroll
        for (int rr = 0; rr < 8; rr++) {
            int idx = tid + 256 * rr;
            int cp = idx & 31, tc = idx >> 5;
            float2 av = *(const float2*)&att[(i0 + tc) * CCH + c0 + 2 * cp];
            unsigned hi, lo; split_pair(av.x, av.y, hi, lo);
            Xs[cp][tc] = make_uint2(hi, lo);
        }
#pragma unroll
        for (int rr = 0; rr < 8; rr++) {
            int idx = tid + 256 * rr;
            int o = idx >> 5, cpl = idx & 31;
            Ws[o][cpl] = g_wf[(o0 + o) * 128 + (c0 >> 1) + cpl];
        }
        __syncthreads();
#pragma unroll
        for (int ks = 0; ks < 4; ks++) {
            uint2 a0 = Ws[og + qr][ks * 8 + qc];
            uint2 a1 = Ws[og + qr + 8][ks * 8 + qc];
            uint2 a2 = Ws[og + qr][ks * 8 + qc + 4];
            uint2 a3 = Ws[og + qr + 8][ks * 8 + qc + 4];
            unsigned ahf[4] = {a0.x, a1.x, a2.x, a3.x};
            unsigned alf[4] = {a0.y, a1.y, a2.y, a3.y};
#pragma unroll
            for (int nf = 0; nf < 4; nf++) {
                int tt = t0w + 8 * nf + qr;
                uint2 b0 = Xs[ks * 8 + qc][tt];
                uint2 b1 = Xs[ks * 8 + qc + 4][tt];
                unsigned bh[2] = {b0.x, b1.x};
                unsigned bl[2] = {b0.y, b1.y};
                mma_bf16(acc[nf], ahf, bh);
                mma_bf16(acc[nf], ahf, bl);
                mma_bf16(acc[nf], alf, bh);
            }
        }
        __syncthreads();
    }
#pragma unroll
    for (int nf = 0; nf < 4; nf++)
#pragma unroll
        for (int rp = 0; rp < 2; rp++) {
            int ol = og + qr + rp * 8;
            int t2 = t0w + 8 * nf + 2 * qc;
            float bv = bias[o0 + ol];
            size_t gidx = ((size_t)b * CCH + o0 + ol) * TT + i0 + t2;
            float2 xv = *(const float2*)&x[gidx];
            float2 outv = make_float2(acc[nf][2 * rp] + bv + xv.x,
                                      acc[nf][2 * rp + 1] + bv + xv.y);
            *(float2*)&g_y[gidx] = outv;
        }
}

__global__ void k5_gnstats() {
    int bid = blockIdx.x, b = bid >> 4, g = bid & 15;
    const float* yp = g_y + ((size_t)(b * CCH + g * 16)) * TT;
    int tid = threadIdx.x;
    float s = 0.f, sq = 0.f;
    for (int idx = tid; idx < 16 * TT; idx += 256) { float v = yp[idx]; s += v; sq += v * v; }
#pragma unroll
    for (int off = 16; off > 0; off >>= 1) {
        s  += __shfl_down_sync(0xffffffffu, s, off);
        sq += __shfl_down_sync(0xffffffffu, sq, off);
    }
    __shared__ float rs[8], rq[8];
    if ((tid & 31) == 0) { rs[tid >> 5] = s; rq[tid >> 5] = sq; }
    __syncthreads();
    if (tid == 0) {
        float S = 0.f, Q = 0.f;
#pragma unroll
        for (int w = 0; w < 8; w++) { S += rs[w]; Q += rq[w]; }
        float mu = S / 9216.f;
        float var = Q / 9216.f - mu * mu;
        g_mu[bid] = mu;
        g_rstd[bid] = rsqrtf(var + GN_EPS);
    }
}

__global__ void k6_gnapply(float* __restrict__ out, const float* __restrict__ gw,
                           const float* __restrict__ gb) {
    int idx = blockIdx.x * 256 + threadIdx.x;
    int o = (idx / TT) & 255;
    int b = idx / (TT * CCH);
    float mu = g_mu[b * 16 + (o >> 4)], rstd = g_rstd[b * 16 + (o >> 4)];
    out[idx] = (g_y[idx] - mu) * rstd * gw[o] + gb[o];
}

extern "C" void kernel_launch(void* const* d_in, const int* in_sizes, int n_in,
                              void* d_out, int out_size) {
    const float* x     = (const float*)d_in[0];
    const float* qkv_w = (const float*)d_in[1];
    const float* qkv_b = (const float*)d_in[2];
    const float* rh_k  = (const float*)d_in[3];
    const float* rw_k  = (const float*)d_in[4];
    const float* rh_v  = (const float*)d_in[5];
    const float* rw_v  = (const float*)d_in[6];
    const float* fc_w  = (const float*)d_in[7];
    const float* fc_b  = (const float*)d_in[8];
    const float* gn_w  = (const float*)d_in[9];
    const float* gn_b  = (const float*)d_in[10];
    float* out = (float*)d_out;

    cudaFuncSetAttribute(k3_attn, cudaFuncAttributeMaxDynamicSharedMemorySize, 64512);

    k0_prep<<<607, 256>>>(rh_v, rw_v, rh_k, rw_k, qkv_w, fc_w);
    k1_qkv<<<dim3(9, 12, BB), 256>>>(x, qkv_b);
    kE_gemm<<<dim3(9, 128), 256>>>();
    k3_attn<<<dim3(36, BB), 256, 64512>>>();
    k4_fc<<<dim3(9, 4, BB), 256>>>(x, fc_b);
    k5_gnstats<<<256, 256>>>();
    k6_gnapply<<<9216, 256>>>(out, gn_w, gn_b);
}

// round 16
// speedup vs baseline: 1.1478x; 1.1478x over previous
#include <cuda_runtime.h>
#include <cuda_bf16.h>
#include <math.h>

#define BB 16
#define CCH 256
#define TT 576
#define NH 8
#define QSCALE 0.17677669529663687f
#define GN_EPS 1e-5f
#define ZS 17
#define JPS 17

__device__ float g_qt[BB * NH * TT * 32];
__device__ uint2 g_k[BB * NH * TT * 16];      // (hi,lo) bf16x2 d-pairs, [bn][t][dp]
__device__ uint2 g_v[BB * NH * 32 * 288];     // (hi,lo) bf16x2 j-pairs, [bn][d][jp]
__device__ uint2 g_wq[768 * 128];             // pre-split qkv_w, pairs along c
__device__ uint2 g_wf[256 * 128];             // pre-split fc_w, pairs along c
__device__ float g_E[BB * NH * TT * 48];
__device__ float g_P[48 * 256];
__device__ float g_R[NH * 47 * 32];
__device__ float g_att[BB * TT * CCH];
__device__ float g_y[BB * CCH * TT];

__device__ __forceinline__ unsigned pack_bf16(float x, float y) {
    __nv_bfloat162 t = __floats2bfloat162_rn(x, y);
    return *reinterpret_cast<unsigned*>(&t);
}
__device__ __forceinline__ void split_pair(float x, float y, unsigned& hi, unsigned& lo) {
    float xh = __bfloat162float(__float2bfloat16_rn(x));
    float yh = __bfloat162float(__float2bfloat16_rn(y));
    hi = pack_bf16(xh, yh);
    lo = pack_bf16(x - xh, y - yh);
}
__device__ __forceinline__ void mma_bf16(float* d, const unsigned* a, const unsigned* b) {
    asm volatile("mma.sync.aligned.m16n8k16.row.col.f32.bf16.bf16.f32 "
                 "{%0,%1,%2,%3},{%4,%5,%6,%7},{%8,%9},{%0,%1,%2,%3};"
                 : "+f"(d[0]), "+f"(d[1]), "+f"(d[2]), "+f"(d[3])
                 : "r"(a[0]), "r"(a[1]), "r"(a[2]), "r"(a[3]), "r"(b[0]), "r"(b[1]));
}

// ---------- k0: P, R tables + weight pre-splits ----------
__global__ void k0_prep(const float* __restrict__ rh_v, const float* __restrict__ rw_v,
                        const float* __restrict__ rh_k, const float* __restrict__ rw_k,
                        const float* __restrict__ qkv_w, const float* __restrict__ fc_w) {
    int bx = blockIdx.x, tid = threadIdx.x;
    if (bx < 48) {
        int idx = bx * 256 + tid;
        int m = idx >> 8, rest = idx & 255;
        g_P[idx] = (m > 0) ? (rh_v[(m - 1) * 256 + rest] + rw_v[(m - 1) * 256 + rest]) : 0.f;
    } else if (bx < 95) {
        int l = bx - 48;
        int n = tid >> 5, d = tid & 31;
        g_R[(n * 47 + l) * 32 + d] = rh_k[(l * 8 + n) * 32 + d] + rw_k[(l * 8 + n) * 32 + d];
    } else if (bx < 479) {
        int idx = (bx - 95) * 256 + tid;      // 384 blocks: 768*128 pairs
        int o = idx >> 7, cp = idx & 127;
        unsigned hi, lo;
        split_pair(qkv_w[o * 256 + 2 * cp], qkv_w[o * 256 + 2 * cp + 1], hi, lo);
        g_wq[idx] = make_uint2(hi, lo);
    } else {
        int idx = (bx - 479) * 256 + tid;     // 128 blocks: 256*128 pairs
        int o = idx >> 7, cp = idx & 127;
        unsigned hi, lo;
        split_pair(fc_w[o * 256 + 2 * cp], fc_w[o * 256 + 2 * cp + 1], hi, lo);
        g_wf[idx] = make_uint2(hi, lo);
    }
}

// ---------- k1: qkv GEMM via bf16-split mma; epilogue emits q f32 / k,v split ----------
__global__ __launch_bounds__(256) void k1_qkv(const float* __restrict__ x,
                                              const float* __restrict__ bias) {
    __shared__ uint2 Xs[32][66];    // x pairs: [cp][t]
    __shared__ uint2 Ws[64][33];    // w pairs: [o][cp]
    __shared__ float Ts[64][68];    // output staging [t][o]
    int b = blockIdx.z, o0 = blockIdx.y * 64, i0 = blockIdx.x * 64;
    int tid = threadIdx.x, warp = tid >> 5, lane = tid & 31;
    int qr = lane >> 2, qc = lane & 3;
    int og = (warp >> 1) * 16;
    int t0w = (warp & 1) * 32;
    const float* xb = x + (size_t)b * CCH * TT;
    float acc[4][4] = {};

    for (int c0 = 0; c0 < 256; c0 += 64) {
#pragma unroll
        for (int rr = 0; rr < 8; rr++) {
            int idx = tid + 256 * rr;
            int cp = idx >> 6, tc = idx & 63;
            float x0 = xb[(c0 + 2 * cp) * TT + i0 + tc];
            float x1 = xb[(c0 + 2 * cp + 1) * TT + i0 + tc];
            unsigned hi, lo; split_pair(x0, x1, hi, lo);
            Xs[cp][tc] = make_uint2(hi, lo);
        }
#pragma unroll
        for (int rr = 0; rr < 8; rr++) {
            int idx = tid + 256 * rr;
            int o = idx >> 5, cpl = idx & 31;
            Ws[o][cpl] = g_wq[(o0 + o) * 128 + (c0 >> 1) + cpl];
        }
        __syncthreads();
#pragma unroll
        for (int ks = 0; ks < 4; ks++) {
            uint2 a0 = Ws[og + qr][ks * 8 + qc];
            uint2 a1 = Ws[og + qr + 8][ks * 8 + qc];
            uint2 a2 = Ws[og + qr][ks * 8 + qc + 4];
            uint2 a3 = Ws[og + qr + 8][ks * 8 + qc + 4];
            unsigned ahf[4] = {a0.x, a1.x, a2.x, a3.x};
            unsigned alf[4] = {a0.y, a1.y, a2.y, a3.y};
#pragma unroll
            for (int nf = 0; nf < 4; nf++) {
                int tt = t0w + 8 * nf + qr;
                uint2 b0 = Xs[ks * 8 + qc][tt];
                uint2 b1 = Xs[ks * 8 + qc + 4][tt];
                unsigned bh[2] = {b0.x, b1.x};
                unsigned bl[2] = {b0.y, b1.y};
                mma_bf16(acc[nf], ahf, bh);
                mma_bf16(acc[nf], ahf, bl);
                mma_bf16(acc[nf], alf, bh);
            }
        }
        __syncthreads();
    }
#pragma unroll
    for (int nf = 0; nf < 4; nf++)
#pragma unroll
        for (int r = 0; r < 4; r++) {
            int ol = og + qr + (r >> 1) * 8;
            int tl = t0w + 8 * nf + 2 * qc + (r & 1);
            Ts[tl][ol] = acc[nf][r] + bias[o0 + ol];
        }
    __syncthreads();
    int sec = o0 >> 8;                  // 0=q, 1=k, 2=v
    int h0 = (o0 & 255) >> 5;
    if (sec == 0) {
        int tl_ = tid >> 2, quad = tid & 3;
#pragma unroll
        for (int k4 = 0; k4 < 4; k4++) {
            int ol = quad * 16 + k4 * 4;
            int head = h0 + (ol >> 5);
            int d = ol & 31;
            float4 v = *(const float4*)&Ts[tl_][ol];
            *(float4*)&g_qt[(((size_t)b * NH + head) * TT + i0 + tl_) * 32 + d] = v;
        }
    } else if (sec == 1) {
#pragma unroll
        for (int wI = 0; wI < 8; wI++) {
            int idx = tid + 256 * wI;
            int hh = idx >> 10, tl = (idx >> 4) & 63, dp = idx & 15;
            float xv = Ts[tl][hh * 32 + 2 * dp], yv = Ts[tl][hh * 32 + 2 * dp + 1];
            unsigned hi, lo; split_pair(xv, yv, hi, lo);
            size_t a = (((size_t)b * NH + h0 + hh) * TT + i0 + tl) * 16 + dp;
            g_k[a] = make_uint2(hi, lo);
        }
    } else {
#pragma unroll
        for (int wI = 0; wI < 8; wI++) {
            int idx = tid + 256 * wI;
            int hh = idx >> 10, dd = (idx >> 5) & 31, jp = idx & 31;
            float xv = Ts[2 * jp][hh * 32 + dd], yv = Ts[2 * jp + 1][hh * 32 + dd];
            unsigned hi, lo; split_pair(xv, yv, hi, lo);
            size_t a = (((size_t)b * NH + h0 + hh) * 32 + dd) * 288 + (i0 >> 1) + jp;
            g_v[a] = make_uint2(hi, lo);
        }
    }
}

// ---------- kE ----------
__global__ __launch_bounds__(256) void kE_gemm() {
    __shared__ float Qs[64][36];
    __shared__ float Rs[48][36];
    int bn = blockIdx.y;
    int iu0 = blockIdx.x * 64;
    int n = bn & 7;
    int tid = threadIdx.x;
    const float* qsrc = g_qt + ((size_t)bn * TT + iu0) * 32;
    for (int idx = tid; idx < 64 * 32; idx += 256) Qs[idx >> 5][idx & 31] = qsrc[idx];
    for (int idx = tid; idx < 48 * 32; idx += 256) {
        int r = idx >> 5, d = idx & 31;
        Rs[r][d] = (r < 47) ? g_R[(n * 47 + r) * 32 + d] : 0.f;
    }
    __syncthreads();
    int tl = tid & 15, tiu = tid >> 4;
    float acc[4][3] = {};
#pragma unroll
    for (int d4 = 0; d4 < 8; d4++) {
        float4 q4[4], r4[3];
#pragma unroll
        for (int r = 0; r < 4; r++) q4[r] = *(const float4*)&Qs[tiu * 4 + r][d4 * 4];
#pragma unroll
        for (int j = 0; j < 3; j++) r4[j] = *(const float4*)&Rs[tl * 3 + j][d4 * 4];
#pragma unroll
        for (int r = 0; r < 4; r++)
#pragma unroll
            for (int j = 0; j < 3; j++)
                acc[r][j] += q4[r].x * r4[j].x + q4[r].y * r4[j].y +
                             q4[r].z * r4[j].z + q4[r].w * r4[j].w;
    }
    float* ep = g_E + ((size_t)bn * TT + iu0) * 48;
#pragma unroll
    for (int r = 0; r < 4; r++)
#pragma unroll
        for (int j = 0; j < 3; j++)
            ep[(tiu * 4 + r) * 48 + tl * 3 + j] = acc[r][j];
}

// ---------- k3: fused attention (reverted to proven 2 CTAs/SM, 128 regs) ----------
__global__ __launch_bounds__(256, 2) void k3_attn() {
    extern __shared__ float sm[];
    float* z_s  = sm;                          // [8][32][ZS]  4352 floats
    uint2* za   = (uint2*)(sm + 4352);         // [8][16][JPS] 2176 uint2
    float* A_s  = sm + 4352 + 4352;            // [8][16][25]  3200 floats
    float* bd_s = A_s + 3200;                  // [8][16][24]  3072 floats
    uint2* Ssm  = (uint2*)(bd_s + 3072);       // [3][2][3][32] 576 uint2
    int b = blockIdx.y, i0 = blockIdx.x * 16;
    int tid = threadIdx.x, warp = tid >> 5, lane = tid & 31;
    int n = warp, bn = b * NH + n;
    int qr = lane >> 2, qc = lane & 3;

    for (int idx = tid; idx < 8 * 16 * 24; idx += 256) {
        int nn = idx / 384, r = idx % 384, ii = r / 24, c = r % 24;
        int ig = i0 + ii;
        int diff = c - ig;
        int fl = (diff >= 0) ? 0 : -((-diff + 47) / 48);
        int l = diff - 48 * fl;
        int iu = 12 + ig + fl;
        bd_s[idx] = l ? g_E[(((size_t)b * NH + nn) * TT + iu) * 48 + (l - 1)] : 0.f;
    }
    for (int idx = tid; idx < 576; idx += 256) {
        int l = idx & 31, rest = idx >> 5;
        int nf = rest % 3, kkc = rest / 3;
        int kk = kkc & 1, jcls = kkc >> 1;
        int qr_ = l >> 2, qc_ = l & 3;
        int jm0 = (8 * jcls + 16 * kk + 2 * qc_) % 24;
        int jm1 = (jm0 + 1) % 24;
        int jm8 = (jm0 + 8) % 24;
        int jm9 = (jm8 + 1) % 24;
        int cg = 8 * nf + qr_;
        Ssm[idx] = make_uint2(pack_bf16(jm0 == cg ? 1.f : 0.f, jm1 == cg ? 1.f : 0.f),
                              pack_bf16(jm8 == cg ? 1.f : 0.f, jm9 == cg ? 1.f : 0.f));
    }

    unsigned qh[2][4], ql[2][4];
#pragma unroll
    for (int kk = 0; kk < 2; kk++)
#pragma unroll
        for (int r = 0; r < 4; r++) {
            int row = i0 + qr + (r & 1) * 8;
            int col = 16 * kk + 2 * qc + (r >> 1) * 8;
            float2 v = *(const float2*)&g_qt[((size_t)bn * TT + row) * 32 + col];
            split_pair(v.x, v.y, qh[kk][r], ql[kk][r]);
        }

    const uint2* kb = g_k + (size_t)bn * TT * 16;
    const uint2* vb = g_v + (size_t)bn * 32 * 288;

    float oacc[4][4];
#pragma unroll
    for (int df = 0; df < 4; df++)
#pragma unroll
        for (int r = 0; r < 4; r++) oacc[df][r] = 0.f;
    float cA[3][4];
#pragma unroll
    for (int nf = 0; nf < 3; nf++)
#pragma unroll
        for (int r = 0; r < 4; r++) cA[nf][r] = 0.f;
    __syncthreads();

    for (int jt = 0; jt < TT; jt += 32) {
        int jtc = jt % 24;
        int jcls = (jt >> 5) % 3;
#pragma unroll
        for (int jf = 0; jf < 4; jf++) {
            float z[4] = {0.f, 0.f, 0.f, 0.f};
#pragma unroll
            for (int kk = 0; kk < 2; kk++) {
                unsigned base = (unsigned)(jt + 8 * jf + qr) * 16u + qc + 8 * kk;
                uint2 w0 = kb[base], w1 = kb[base + 4];
                unsigned bh[2] = {w0.x, w1.x};
                unsigned bl[2] = {w0.y, w1.y};
                mma_bf16(z, qh[kk], bh);
                mma_bf16(z, qh[kk], bl);
                mma_bf16(z, ql[kk], bh);
            }
            int jl0 = 8 * jf + 2 * qc;
            int c0 = jtc + jl0;     if (c0 >= 24) c0 -= 24; if (c0 >= 24) c0 -= 24;
            int c1 = jtc + jl0 + 1; if (c1 >= 24) c1 -= 24; if (c1 >= 24) c1 -= 24;
            z[0] += bd_s[(n * 16 + qr) * 24 + c0];
            z[1] += bd_s[(n * 16 + qr) * 24 + c1];
            z[2] += bd_s[(n * 16 + qr + 8) * 24 + c0];
            z[3] += bd_s[(n * 16 + qr + 8) * 24 + c1];
            z_s[(n * 32 + jl0) * ZS + qr]         = z[0];
            z_s[(n * 32 + jl0 + 1) * ZS + qr]     = z[1];
            z_s[(n * 32 + jl0) * ZS + qr + 8]     = z[2];
            z_s[(n * 32 + jl0 + 1) * ZS + qr + 8] = z[3];
        }
        __syncthreads();
        {
            int jp = tid & 15, i = tid >> 4;
            int j0 = 2 * jp;
            float z0[8], z1[8];
#pragma unroll
            for (int m = 0; m < 8; m++) {
                z0[m] = z_s[(m * 32 + j0) * ZS + i] * QSCALE;
                z1[m] = z_s[(m * 32 + j0 + 1) * ZS + i] * QSCALE;
            }
            float mx0 = z0[0], mx1 = z1[0];
#pragma unroll
            for (int m = 1; m < 8; m++) { mx0 = fmaxf(mx0, z0[m]); mx1 = fmaxf(mx1, z1[m]); }
            float s0 = 0.f, s1 = 0.f;
#pragma unroll
            for (int m = 0; m < 8; m++) {
                z0[m] = __expf(z0[m] - mx0); s0 += z0[m];
                z1[m] = __expf(z1[m] - mx1); s1 += z1[m];
            }
            float inv0 = 1.f / s0, inv1 = 1.f / s1;
#pragma unroll
            for (int m = 0; m < 8; m++) {
                unsigned hi, lo;
                split_pair(z0[m] * inv0, z1[m] * inv1, hi, lo);
                za[(m * 16 + i) * JPS + jp] = make_uint2(hi, lo);
            }
        }
        __syncthreads();
        unsigned ah[2][4], al[2][4];
#pragma unroll
        for (int kk = 0; kk < 2; kk++)
#pragma unroll
            for (int r = 0; r < 4; r++) {
                int jp = 8 * kk + qc + (r >> 1) * 4;
                int ir = qr + (r & 1) * 8;
                uint2 wv = za[(n * 16 + ir) * JPS + jp];
                ah[kk][r] = wv.x; al[kk][r] = wv.y;
            }
#pragma unroll
        for (int kk = 0; kk < 2; kk++) {
#pragma unroll
            for (int nf = 0; nf < 3; nf++) {
                uint2 sv = Ssm[((jcls * 2 + kk) * 3 + nf) * 32 + lane];
                unsigned sb[2] = {sv.x, sv.y};
                mma_bf16(cA[nf], ah[kk], sb);
                mma_bf16(cA[nf], al[kk], sb);
            }
        }
#pragma unroll
        for (int df = 0; df < 4; df++) {
#pragma unroll
            for (int kk = 0; kk < 2; kk++) {
                unsigned base = (unsigned)(qr + 8 * df) * 288u + (jt >> 1) + qc + 8 * kk;
                uint2 w0 = vb[base], w1 = vb[base + 4];
                unsigned bh[2] = {w0.x, w1.x};
                unsigned bl[2] = {w0.y, w1.y};
                mma_bf16(oacc[df], ah[kk], bh);
                mma_bf16(oacc[df], ah[kk], bl);
                mma_bf16(oacc[df], al[kk], bh);
            }
        }
    }
#pragma unroll
    for (int nf = 0; nf < 3; nf++) {
        int cg = 8 * nf + 2 * qc;
        A_s[(n * 16 + qr) * 25 + cg]         = cA[nf][0];
        A_s[(n * 16 + qr) * 25 + cg + 1]     = cA[nf][1];
        A_s[(n * 16 + qr + 8) * 25 + cg]     = cA[nf][2];
        A_s[(n * 16 + qr + 8) * 25 + cg + 1] = cA[nf][3];
    }
    __syncwarp();
#pragma unroll
    for (int df = 0; df < 4; df++)
#pragma unroll
        for (int r = 0; r < 4; r++) {
            int ii = qr + (r >> 1) * 8;
            int d  = 8 * df + 2 * qc + (r & 1);
            int ig = i0 + ii;
            float o2 = 0.f;
#pragma unroll
            for (int c = 0; c < 24; c++) {
                int m = (c - ig) % 48; if (m < 0) m += 48;
                o2 += A_s[(n * 16 + ii) * 25 + c] * g_P[m * 256 + n * 32 + d];
            }
            g_att[((size_t)b * TT + ig) * CCH + n * 32 + d] = oacc[df][r] + o2;
        }
}

// ---------- k4: fc GEMM via bf16-split mma + residual ----------
__global__ __launch_bounds__(256) void k4_fc(const float* __restrict__ x,
                                             const float* __restrict__ bias) {
    __shared__ uint2 Xs[32][67];    // att pairs: [cp][t]
    __shared__ uint2 Ws[64][33];    // w pairs: [o][cp]
    int b = blockIdx.z, o0 = blockIdx.y * 64, i0 = blockIdx.x * 64;
    int tid = threadIdx.x, warp = tid >> 5, lane = tid & 31;
    int qr = lane >> 2, qc = lane & 3;
    int og = (warp >> 1) * 16;
    int t0w = (warp & 1) * 32;
    const float* att = g_att + (size_t)b * TT * CCH;
    float acc[4][4] = {};

    for (int c0 = 0; c0 < 256; c0 += 64) {
#pragma unroll
        for (int rr = 0; rr < 8; rr++) {
            int idx = tid + 256 * rr;
            int cp = idx & 31, tc = idx >> 5;
            float2 av = *(const float2*)&att[(i0 + tc) * CCH + c0 + 2 * cp];
            unsigned hi, lo; split_pair(av.x, av.y, hi, lo);
            Xs[cp][tc] = make_uint2(hi, lo);
        }
#pragma unroll
        for (int rr = 0; rr < 8; rr++) {
            int idx = tid + 256 * rr;
            int o = idx >> 5, cpl = idx & 31;
            Ws[o][cpl] = g_wf[(o0 + o) * 128 + (c0 >> 1) + cpl];
        }
        __syncthreads();
#pragma unroll
        for (int ks = 0; ks < 4; ks++) {
            uint2 a0 = Ws[og + qr][ks * 8 + qc];
            uint2 a1 = Ws[og + qr + 8][ks * 8 + qc];
            uint2 a2 = Ws[og + qr][ks * 8 + qc + 4];
            uint2 a3 = Ws[og + qr + 8][ks * 8 + qc + 4];
            unsigned ahf[4] = {a0.x, a1.x, a2.x, a3.x};
            unsigned alf[4] = {a0.y, a1.y, a2.y, a3.y};
#pragma unroll
            for (int nf = 0; nf < 4; nf++) {
                int tt = t0w + 8 * nf + qr;
                uint2 b0 = Xs[ks * 8 + qc][tt];
                uint2 b1 = Xs[ks * 8 + qc + 4][tt];
                unsigned bh[2] = {b0.x, b1.x};
                unsigned bl[2] = {b0.y, b1.y};
                mma_bf16(acc[nf], ahf, bh);
                mma_bf16(acc[nf], ahf, bl);
                mma_bf16(acc[nf], alf, bh);
            }
        }
        __syncthreads();
    }
#pragma unroll
    for (int nf = 0; nf < 4; nf++)
#pragma unroll
        for (int rp = 0; rp < 2; rp++) {
            int ol = og + qr + rp * 8;
            int t2 = t0w + 8 * nf + 2 * qc;
            float bv = bias[o0 + ol];
            size_t gidx = ((size_t)b * CCH + o0 + ol) * TT + i0 + t2;
            float2 xv = *(const float2*)&x[gidx];
            float2 outv = make_float2(acc[nf][2 * rp] + bv + xv.x,
                                      acc[nf][2 * rp + 1] + bv + xv.y);
            *(float2*)&g_y[gidx] = outv;
        }
}

// ---------- k56: fused GroupNorm (stats + apply) ----------
__global__ __launch_bounds__(256) void k56_gn(float* __restrict__ out,
                                              const float* __restrict__ gw,
                                              const float* __restrict__ gb) {
    int bid = blockIdx.x, b = bid >> 4, g = bid & 15;
    size_t base = ((size_t)(b * CCH + g * 16)) * TT;
    const float* yp = g_y + base;
    int tid = threadIdx.x;
    float s = 0.f, sq = 0.f;
    for (int idx = tid; idx < 16 * TT; idx += 256) { float v = yp[idx]; s += v; sq += v * v; }
#pragma unroll
    for (int off = 16; off > 0; off >>= 1) {
        s  += __shfl_down_sync(0xffffffffu, s, off);
        sq += __shfl_down_sync(0xffffffffu, sq, off);
    }
    __shared__ float rs[8], rq[8];
    __shared__ float s_mu, s_rstd;
    if ((tid & 31) == 0) { rs[tid >> 5] = s; rq[tid >> 5] = sq; }
    __syncthreads();
    if (tid == 0) {
        float S = 0.f, Q = 0.f;
#pragma unroll
        for (int w = 0; w < 8; w++) { S += rs[w]; Q += rq[w]; }
        float mu = S / 9216.f;
        float var = Q / 9216.f - mu * mu;
        s_mu = mu;
        s_rstd = rsqrtf(var + GN_EPS);
    }
    __syncthreads();
    float mu = s_mu, rstd = s_rstd;
    for (int idx = tid; idx < 16 * TT; idx += 256) {
        int o = g * 16 + idx / TT;
        out[base + idx] = (yp[idx] - mu) * rstd * gw[o] + gb[o];
    }
}

extern "C" void kernel_launch(void* const* d_in, const int* in_sizes, int n_in,
                              void* d_out, int out_size) {
    const float* x     = (const float*)d_in[0];
    const float* qkv_w = (const float*)d_in[1];
    const float* qkv_b = (const float*)d_in[2];
    const float* rh_k  = (const float*)d_in[3];
    const float* rw_k  = (const float*)d_in[4];
    const float* rh_v  = (const float*)d_in[5];
    const float* rw_v  = (const float*)d_in[6];
    const float* fc_w  = (const float*)d_in[7];
    const float* fc_b  = (const float*)d_in[8];
    const float* gn_w  = (const float*)d_in[9];
    const float* gn_b  = (const float*)d_in[10];
    float* out = (float*)d_out;

    cudaFuncSetAttribute(k3_attn, cudaFuncAttributeMaxDynamicSharedMemorySize, 64512);

    k0_prep<<<607, 256>>>(rh_v, rw_v, rh_k, rw_k, qkv_w, fc_w);
    k1_qkv<<<dim3(9, 12, BB), 256>>>(x, qkv_b);
    kE_gemm<<<dim3(9, 128), 256>>>();
    k3_attn<<<dim3(36, BB), 256, 64512>>>();
    k4_fc<<<dim3(9, 4, BB), 256>>>(x, fc_b);
    k56_gn<<<256, 256>>>(out, gn_w, gn_b);
}

// round 17
// speedup vs baseline: 1.1703x; 1.0197x over previous
#include <cuda_runtime.h>
#include <cuda_bf16.h>
#include <math.h>

#define BB 16
#define CCH 256
#define TT 576
#define NH 8
#define QSCALE 0.17677669529663687f
#define GN_EPS 1e-5f
#define ZS 17
#define JP2S 33

__device__ float g_qt[BB * NH * TT * 32];
__device__ uint2 g_k[BB * NH * TT * 16];      // (hi,lo) bf16x2 d-pairs, [bn][t][dp]
__device__ uint2 g_v[BB * NH * 32 * 288];     // (hi,lo) bf16x2 j-pairs, [bn][d][jp]
__device__ uint2 g_wq[768 * 128];             // pre-split qkv_w, pairs along c
__device__ uint2 g_wf[256 * 128];             // pre-split fc_w, pairs along c
__device__ float g_E[BB * NH * TT * 48];
__device__ float g_P[48 * 256];
__device__ float g_R[NH * 47 * 32];
__device__ float g_att[BB * TT * CCH];
__device__ float g_y[BB * CCH * TT];

__device__ __forceinline__ unsigned pack_bf16(float x, float y) {
    __nv_bfloat162 t = __floats2bfloat162_rn(x, y);
    return *reinterpret_cast<unsigned*>(&t);
}
__device__ __forceinline__ void split_pair(float x, float y, unsigned& hi, unsigned& lo) {
    float xh = __bfloat162float(__float2bfloat16_rn(x));
    float yh = __bfloat162float(__float2bfloat16_rn(y));
    hi = pack_bf16(xh, yh);
    lo = pack_bf16(x - xh, y - yh);
}
__device__ __forceinline__ void mma_bf16(float* d, const unsigned* a, const unsigned* b) {
    asm volatile("mma.sync.aligned.m16n8k16.row.col.f32.bf16.bf16.f32 "
                 "{%0,%1,%2,%3},{%4,%5,%6,%7},{%8,%9},{%0,%1,%2,%3};"
                 : "+f"(d[0]), "+f"(d[1]), "+f"(d[2]), "+f"(d[3])
                 : "r"(a[0]), "r"(a[1]), "r"(a[2]), "r"(a[3]), "r"(b[0]), "r"(b[1]));
}

// ---------- k0: P, R tables + weight pre-splits ----------
__global__ void k0_prep(const float* __restrict__ rh_v, const float* __restrict__ rw_v,
                        const float* __restrict__ rh_k, const float* __restrict__ rw_k,
                        const float* __restrict__ qkv_w, const float* __restrict__ fc_w) {
    int bx = blockIdx.x, tid = threadIdx.x;
    if (bx < 48) {
        int idx = bx * 256 + tid;
        int m = idx >> 8, rest = idx & 255;
        g_P[idx] = (m > 0) ? (rh_v[(m - 1) * 256 + rest] + rw_v[(m - 1) * 256 + rest]) : 0.f;
    } else if (bx < 95) {
        int l = bx - 48;
        int n = tid >> 5, d = tid & 31;
        g_R[(n * 47 + l) * 32 + d] = rh_k[(l * 8 + n) * 32 + d] + rw_k[(l * 8 + n) * 32 + d];
    } else if (bx < 479) {
        int idx = (bx - 95) * 256 + tid;      // 384 blocks: 768*128 pairs
        int o = idx >> 7, cp = idx & 127;
        unsigned hi, lo;
        split_pair(qkv_w[o * 256 + 2 * cp], qkv_w[o * 256 + 2 * cp + 1], hi, lo);
        g_wq[idx] = make_uint2(hi, lo);
    } else {
        int idx = (bx - 479) * 256 + tid;     // 128 blocks: 256*128 pairs
        int o = idx >> 7, cp = idx & 127;
        unsigned hi, lo;
        split_pair(fc_w[o * 256 + 2 * cp], fc_w[o * 256 + 2 * cp + 1], hi, lo);
        g_wf[idx] = make_uint2(hi, lo);
    }
}

// ---------- k1: qkv GEMM via bf16-split mma; epilogue emits q f32 / k,v split ----------
__global__ __launch_bounds__(256) void k1_qkv(const float* __restrict__ x,
                                              const float* __restrict__ bias) {
    __shared__ uint2 Xs[32][66];    // x pairs: [cp][t]
    __shared__ uint2 Ws[64][33];    // w pairs: [o][cp]
    __shared__ float Ts[64][68];    // output staging [t][o]
    int b = blockIdx.z, o0 = blockIdx.y * 64, i0 = blockIdx.x * 64;
    int tid = threadIdx.x, warp = tid >> 5, lane = tid & 31;
    int qr = lane >> 2, qc = lane & 3;
    int og = (warp >> 1) * 16;
    int t0w = (warp & 1) * 32;
    const float* xb = x + (size_t)b * CCH * TT;
    float acc[4][4] = {};

    for (int c0 = 0; c0 < 256; c0 += 64) {
#pragma unroll
        for (int rr = 0; rr < 8; rr++) {
            int idx = tid + 256 * rr;
            int cp = idx >> 6, tc = idx & 63;
            float x0 = xb[(c0 + 2 * cp) * TT + i0 + tc];
            float x1 = xb[(c0 + 2 * cp + 1) * TT + i0 + tc];
            unsigned hi, lo; split_pair(x0, x1, hi, lo);
            Xs[cp][tc] = make_uint2(hi, lo);
        }
#pragma unroll
        for (int rr = 0; rr < 8; rr++) {
            int idx = tid + 256 * rr;
            int o = idx >> 5, cpl = idx & 31;
            Ws[o][cpl] = g_wq[(o0 + o) * 128 + (c0 >> 1) + cpl];
        }
        __syncthreads();
#pragma unroll
        for (int ks = 0; ks < 4; ks++) {
            uint2 a0 = Ws[og + qr][ks * 8 + qc];
            uint2 a1 = Ws[og + qr + 8][ks * 8 + qc];
            uint2 a2 = Ws[og + qr][ks * 8 + qc + 4];
            uint2 a3 = Ws[og + qr + 8][ks * 8 + qc + 4];
            unsigned ahf[4] = {a0.x, a1.x, a2.x, a3.x};
            unsigned alf[4] = {a0.y, a1.y, a2.y, a3.y};
#pragma unroll
            for (int nf = 0; nf < 4; nf++) {
                int tt = t0w + 8 * nf + qr;
                uint2 b0 = Xs[ks * 8 + qc][tt];
                uint2 b1 = Xs[ks * 8 + qc + 4][tt];
                unsigned bh[2] = {b0.x, b1.x};
                unsigned bl[2] = {b0.y, b1.y};
                mma_bf16(acc[nf], ahf, bh);
                mma_bf16(acc[nf], ahf, bl);
                mma_bf16(acc[nf], alf, bh);
            }
        }
        __syncthreads();
    }
#pragma unroll
    for (int nf = 0; nf < 4; nf++)
#pragma unroll
        for (int r = 0; r < 4; r++) {
            int ol = og + qr + (r >> 1) * 8;
            int tl = t0w + 8 * nf + 2 * qc + (r & 1);
            Ts[tl][ol] = acc[nf][r] + bias[o0 + ol];
        }
    __syncthreads();
    int sec = o0 >> 8;                  // 0=q, 1=k, 2=v
    int h0 = (o0 & 255) >> 5;
    if (sec == 0) {
        int tl_ = tid >> 2, quad = tid & 3;
#pragma unroll
        for (int k4 = 0; k4 < 4; k4++) {
            int ol = quad * 16 + k4 * 4;
            int head = h0 + (ol >> 5);
            int d = ol & 31;
            float4 v = *(const float4*)&Ts[tl_][ol];
            *(float4*)&g_qt[(((size_t)b * NH + head) * TT + i0 + tl_) * 32 + d] = v;
        }
    } else if (sec == 1) {
#pragma unroll
        for (int wI = 0; wI < 8; wI++) {
            int idx = tid + 256 * wI;
            int hh = idx >> 10, tl = (idx >> 4) & 63, dp = idx & 15;
            float xv = Ts[tl][hh * 32 + 2 * dp], yv = Ts[tl][hh * 32 + 2 * dp + 1];
            unsigned hi, lo; split_pair(xv, yv, hi, lo);
            size_t a = (((size_t)b * NH + h0 + hh) * TT + i0 + tl) * 16 + dp;
            g_k[a] = make_uint2(hi, lo);
        }
    } else {
#pragma unroll
        for (int wI = 0; wI < 8; wI++) {
            int idx = tid + 256 * wI;
            int hh = idx >> 10, dd = (idx >> 5) & 31, jp = idx & 31;
            float xv = Ts[2 * jp][hh * 32 + dd], yv = Ts[2 * jp + 1][hh * 32 + dd];
            unsigned hi, lo; split_pair(xv, yv, hi, lo);
            size_t a = (((size_t)b * NH + h0 + hh) * 32 + dd) * 288 + (i0 >> 1) + jp;
            g_v[a] = make_uint2(hi, lo);
        }
    }
}

// ---------- kE ----------
__global__ __launch_bounds__(256) void kE_gemm() {
    __shared__ float Qs[64][36];
    __shared__ float Rs[48][36];
    int bn = blockIdx.y;
    int iu0 = blockIdx.x * 64;
    int n = bn & 7;
    int tid = threadIdx.x;
    const float* qsrc = g_qt + ((size_t)bn * TT + iu0) * 32;
    for (int idx = tid; idx < 64 * 32; idx += 256) Qs[idx >> 5][idx & 31] = qsrc[idx];
    for (int idx = tid; idx < 48 * 32; idx += 256) {
        int r = idx >> 5, d = idx & 31;
        Rs[r][d] = (r < 47) ? g_R[(n * 47 + r) * 32 + d] : 0.f;
    }
    __syncthreads();
    int tl = tid & 15, tiu = tid >> 4;
    float acc[4][3] = {};
#pragma unroll
    for (int d4 = 0; d4 < 8; d4++) {
        float4 q4[4], r4[3];
#pragma unroll
        for (int r = 0; r < 4; r++) q4[r] = *(const float4*)&Qs[tiu * 4 + r][d4 * 4];
#pragma unroll
        for (int j = 0; j < 3; j++) r4[j] = *(const float4*)&Rs[tl * 3 + j][d4 * 4];
#pragma unroll
        for (int r = 0; r < 4; r++)
#pragma unroll
            for (int j = 0; j < 3; j++)
                acc[r][j] += q4[r].x * r4[j].x + q4[r].y * r4[j].y +
                             q4[r].z * r4[j].z + q4[r].w * r4[j].w;
    }
    float* ep = g_E + ((size_t)bn * TT + iu0) * 48;
#pragma unroll
    for (int r = 0; r < 4; r++)
#pragma unroll
        for (int j = 0; j < 3; j++)
            ep[(tiu * 4 + r) * 48 + tl * 3 + j] = acc[r][j];
}

// ---------- k3: fused attention; 64-j tiles (half the barriers, double MLP) ----------
__global__ __launch_bounds__(256, 2) void k3_attn() {
    extern __shared__ float sm[];
    float* z_s  = sm;                          // [8][64][ZS]   8704 floats
    uint2* za   = (uint2*)(sm + 8704);         // [8][16][JP2S] 4224 uint2 (8448 floats)
    float* A_s  = sm + 8704 + 8448;            // [8][16][25]   3200 floats
    float* bd_s = A_s + 3200;                  // [8][16][24]   3072 floats
    uint2* Ssm  = (uint2*)(bd_s + 3072);       // [3][4][3][32] 1152 uint2
    int b = blockIdx.y, i0 = blockIdx.x * 16;
    int tid = threadIdx.x, warp = tid >> 5, lane = tid & 31;
    int n = warp, bn = b * NH + n;
    int qr = lane >> 2, qc = lane & 3;

    for (int idx = tid; idx < 8 * 16 * 24; idx += 256) {
        int nn = idx / 384, r = idx % 384, ii = r / 24, c = r % 24;
        int ig = i0 + ii;
        int diff = c - ig;
        int fl = (diff >= 0) ? 0 : -((-diff + 47) / 48);
        int l = diff - 48 * fl;
        int iu = 12 + ig + fl;
        bd_s[idx] = l ? g_E[(((size_t)b * NH + nn) * TT + iu) * 48 + (l - 1)] : 0.f;
    }
    // S-table: [jcls][kk][nf][lane], kk in 0..3 for 64-j tiles
    for (int idx = tid; idx < 1152; idx += 256) {
        int l = idx & 31, rest = idx >> 5;
        int nf = rest % 3, kkc = rest / 3;
        int kk = kkc & 3, jcls = kkc >> 2;
        int jtc = (jcls == 0) ? 0 : (jcls == 1 ? 16 : 8);   // (64*jcls) % 24
        int qr_ = l >> 2, qc_ = l & 3;
        int jm0 = (jtc + 16 * kk + 2 * qc_) % 24;
        int jm1 = (jm0 + 1) % 24;
        int jm8 = (jm0 + 8) % 24;
        int jm9 = (jm8 + 1) % 24;
        int cg = 8 * nf + qr_;
        Ssm[idx] = make_uint2(pack_bf16(jm0 == cg ? 1.f : 0.f, jm1 == cg ? 1.f : 0.f),
                              pack_bf16(jm8 == cg ? 1.f : 0.f, jm9 == cg ? 1.f : 0.f));
    }

    unsigned qh[2][4], ql[2][4];
#pragma unroll
    for (int kk = 0; kk < 2; kk++)
#pragma unroll
        for (int r = 0; r < 4; r++) {
            int row = i0 + qr + (r & 1) * 8;
            int col = 16 * kk + 2 * qc + (r >> 1) * 8;
            float2 v = *(const float2*)&g_qt[((size_t)bn * TT + row) * 32 + col];
            split_pair(v.x, v.y, qh[kk][r], ql[kk][r]);
        }

    const uint2* kb = g_k + (size_t)bn * TT * 16;
    const uint2* vb = g_v + (size_t)bn * 32 * 288;

    float oacc[4][4];
#pragma unroll
    for (int df = 0; df < 4; df++)
#pragma unroll
        for (int r = 0; r < 4; r++) oacc[df][r] = 0.f;
    float cA[3][4];
#pragma unroll
    for (int nf = 0; nf < 3; nf++)
#pragma unroll
        for (int r = 0; r < 4; r++) cA[nf][r] = 0.f;
    __syncthreads();

    for (int jt = 0; jt < TT; jt += 64) {
        int jtc = jt % 24;
        int jcls = (jt >> 6) % 3;
        // ---- logits via mma, 64 j's (16 front-batched LDG.64) ----
#pragma unroll
        for (int jf = 0; jf < 8; jf++) {
            float z[4] = {0.f, 0.f, 0.f, 0.f};
#pragma unroll
            for (int kk = 0; kk < 2; kk++) {
                unsigned base = (unsigned)(jt + 8 * jf + qr) * 16u + qc + 8 * kk;
                uint2 w0 = kb[base], w1 = kb[base + 4];
                unsigned bh[2] = {w0.x, w1.x};
                unsigned bl[2] = {w0.y, w1.y};
                mma_bf16(z, qh[kk], bh);
                mma_bf16(z, qh[kk], bl);
                mma_bf16(z, ql[kk], bh);
            }
            int jl0 = 8 * jf + 2 * qc;
            int c0 = jtc + jl0;     if (c0 >= 48) c0 -= 48; if (c0 >= 24) c0 -= 24;
            int c1 = jtc + jl0 + 1; if (c1 >= 48) c1 -= 48; if (c1 >= 24) c1 -= 24;
            z[0] += bd_s[(n * 16 + qr) * 24 + c0];
            z[1] += bd_s[(n * 16 + qr) * 24 + c1];
            z[2] += bd_s[(n * 16 + qr + 8) * 24 + c0];
            z[3] += bd_s[(n * 16 + qr + 8) * 24 + c1];
            z_s[(n * 64 + jl0) * ZS + qr]         = z[0];
            z_s[(n * 64 + jl0 + 1) * ZS + qr]     = z[1];
            z_s[(n * 64 + jl0) * ZS + qr + 8]     = z[2];
            z_s[(n * 64 + jl0 + 1) * ZS + qr + 8] = z[3];
        }
        __syncthreads();
        // ---- softmax over heads; 2 j-pairs per thread; emit packed pairs ----
        {
            int jp0 = tid & 15, i = tid >> 4;
#pragma unroll
            for (int p = 0; p < 2; p++) {
                int jp = jp0 + 16 * p;
                int j0 = 2 * jp;
                float z0[8], z1[8];
#pragma unroll
                for (int m = 0; m < 8; m++) {
                    z0[m] = z_s[(m * 64 + j0) * ZS + i] * QSCALE;
                    z1[m] = z_s[(m * 64 + j0 + 1) * ZS + i] * QSCALE;
                }
                float mx0 = z0[0], mx1 = z1[0];
#pragma unroll
                for (int m = 1; m < 8; m++) { mx0 = fmaxf(mx0, z0[m]); mx1 = fmaxf(mx1, z1[m]); }
                float s0 = 0.f, s1 = 0.f;
#pragma unroll
                for (int m = 0; m < 8; m++) {
                    z0[m] = __expf(z0[m] - mx0); s0 += z0[m];
                    z1[m] = __expf(z1[m] - mx1); s1 += z1[m];
                }
                float inv0 = 1.f / s0, inv1 = 1.f / s1;
#pragma unroll
                for (int m = 0; m < 8; m++) {
                    unsigned hi, lo;
                    split_pair(z0[m] * inv0, z1[m] * inv1, hi, lo);
                    za[(m * 16 + i) * JP2S + jp] = make_uint2(hi, lo);
                }
            }
        }
        __syncthreads();
        // ---- per-kk: fragments -> A-sums + attn@v (low register pressure) ----
#pragma unroll
        for (int kk = 0; kk < 4; kk++) {
            unsigned ah[4], al[4];
#pragma unroll
            for (int r = 0; r < 4; r++) {
                int jp = 8 * kk + qc + (r >> 1) * 4;
                int ir = qr + (r & 1) * 8;
                uint2 wv = za[(n * 16 + ir) * JP2S + jp];
                ah[r] = wv.x; al[r] = wv.y;
            }
#pragma unroll
            for (int nf = 0; nf < 3; nf++) {
                uint2 sv = Ssm[((jcls * 4 + kk) * 3 + nf) * 32 + lane];
                unsigned sb[2] = {sv.x, sv.y};
                mma_bf16(cA[nf], ah, sb);
                mma_bf16(cA[nf], al, sb);
            }
#pragma unroll
            for (int df = 0; df < 4; df++) {
                unsigned base = (unsigned)(qr + 8 * df) * 288u + (jt >> 1) + qc + 8 * kk;
                uint2 w0 = vb[base], w1 = vb[base + 4];
                unsigned bh[2] = {w0.x, w1.x};
                unsigned bl[2] = {w0.y, w1.y};
                mma_bf16(oacc[df], ah, bh);
                mma_bf16(oacc[df], ah, bl);
                mma_bf16(oacc[df], al, bh);
            }
        }
    }
#pragma unroll
    for (int nf = 0; nf < 3; nf++) {
        int cg = 8 * nf + 2 * qc;
        A_s[(n * 16 + qr) * 25 + cg]         = cA[nf][0];
        A_s[(n * 16 + qr) * 25 + cg + 1]     = cA[nf][1];
        A_s[(n * 16 + qr + 8) * 25 + cg]     = cA[nf][2];
        A_s[(n * 16 + qr + 8) * 25 + cg + 1] = cA[nf][3];
    }
    __syncwarp();
#pragma unroll
    for (int df = 0; df < 4; df++)
#pragma unroll
        for (int r = 0; r < 4; r++) {
            int ii = qr + (r >> 1) * 8;
            int d  = 8 * df + 2 * qc + (r & 1);
            int ig = i0 + ii;
            float o2 = 0.f;
#pragma unroll
            for (int c = 0; c < 24; c++) {
                int m = (c - ig) % 48; if (m < 0) m += 48;
                o2 += A_s[(n * 16 + ii) * 25 + c] * g_P[m * 256 + n * 32 + d];
            }
            g_att[((size_t)b * TT + ig) * CCH + n * 32 + d] = oacc[df][r] + o2;
        }
}

// ---------- k4: fc GEMM via bf16-split mma + residual ----------
__global__ __launch_bounds__(256) void k4_fc(const float* __restrict__ x,
                                             const float* __restrict__ bias) {
    __shared__ uint2 Xs[32][67];    // att pairs: [cp][t]
    __shared__ uint2 Ws[64][33];    // w pairs: [o][cp]
    int b = blockIdx.z, o0 = blockIdx.y * 64, i0 = blockIdx.x * 64;
    int tid = threadIdx.x, warp = tid >> 5, lane = tid & 31;
    int qr = lane >> 2, qc = lane & 3;
    int og = (warp >> 1) * 16;
    int t0w = (warp & 1) * 32;
    const float* att = g_att + (size_t)b * TT * CCH;
    float acc[4][4] = {};

    for (int c0 = 0; c0 < 256; c0 += 64) {
#pragma unroll
        for (int rr = 0; rr < 8; rr++) {
            int idx = tid + 256 * rr;
            int cp = idx & 31, tc = idx >> 5;
            float2 av = *(const float2*)&att[(i0 + tc) * CCH + c0 + 2 * cp];
            unsigned hi, lo; split_pair(av.x, av.y, hi, lo);
            Xs[cp][tc] = make_uint2(hi, lo);
        }
#pragma unroll
        for (int rr = 0; rr < 8; rr++) {
            int idx = tid + 256 * rr;
            int o = idx >> 5, cpl = idx & 31;
            Ws[o][cpl] = g_wf[(o0 + o) * 128 + (c0 >> 1) + cpl];
        }
        __syncthreads();
#pragma unroll
        for (int ks = 0; ks < 4; ks++) {
            uint2 a0 = Ws[og + qr][ks * 8 + qc];
            uint2 a1 = Ws[og + qr + 8][ks * 8 + qc];
            uint2 a2 = Ws[og + qr][ks * 8 + qc + 4];
            uint2 a3 = Ws[og + qr + 8][ks * 8 + qc + 4];
            unsigned ahf[4] = {a0.x, a1.x, a2.x, a3.x};
            unsigned alf[4] = {a0.y, a1.y, a2.y, a3.y};
#pragma unroll
            for (int nf = 0; nf < 4; nf++) {
                int tt = t0w + 8 * nf + qr;
                uint2 b0 = Xs[ks * 8 + qc][tt];
                uint2 b1 = Xs[ks * 8 + qc + 4][tt];
                unsigned bh[2] = {b0.x, b1.x};
                unsigned bl[2] = {b0.y, b1.y};
                mma_bf16(acc[nf], ahf, bh);
                mma_bf16(acc[nf], ahf, bl);
                mma_bf16(acc[nf], alf, bh);
            }
        }
        __syncthreads();
    }
#pragma unroll
    for (int nf = 0; nf < 4; nf++)
#pragma unroll
        for (int rp = 0; rp < 2; rp++) {
            int ol = og + qr + rp * 8;
            int t2 = t0w + 8 * nf + 2 * qc;
            float bv = bias[o0 + ol];
            size_t gidx = ((size_t)b * CCH + o0 + ol) * TT + i0 + t2;
            float2 xv = *(const float2*)&x[gidx];
            float2 outv = make_float2(acc[nf][2 * rp] + bv + xv.x,
                                      acc[nf][2 * rp + 1] + bv + xv.y);
            *(float2*)&g_y[gidx] = outv;
        }
}

// ---------- k56: fused GroupNorm (stats + apply) ----------
__global__ __launch_bounds__(256) void k56_gn(float* __restrict__ out,
                                              const float* __restrict__ gw,
                                              const float* __restrict__ gb) {
    int bid = blockIdx.x, b = bid >> 4, g = bid & 15;
    size_t base = ((size_t)(b * CCH + g * 16)) * TT;
    const float* yp = g_y + base;
    int tid = threadIdx.x;
    float s = 0.f, sq = 0.f;
    for (int idx = tid; idx < 16 * TT; idx += 256) { float v = yp[idx]; s += v; sq += v * v; }
#pragma unroll
    for (int off = 16; off > 0; off >>= 1) {
        s  += __shfl_down_sync(0xffffffffu, s, off);
        sq += __shfl_down_sync(0xffffffffu, sq, off);
    }
    __shared__ float rs[8], rq[8];
    __shared__ float s_mu, s_rstd;
    if ((tid & 31) == 0) { rs[tid >> 5] = s; rq[tid >> 5] = sq; }
    __syncthreads();
    if (tid == 0) {
        float S = 0.f, Q = 0.f;
#pragma unroll
        for (int w = 0; w < 8; w++) { S += rs[w]; Q += rq[w]; }
        float mu = S / 9216.f;
        float var = Q / 9216.f - mu * mu;
        s_mu = mu;
        s_rstd = rsqrtf(var + GN_EPS);
    }
    __syncthreads();
    float mu = s_mu, rstd = s_rstd;
    for (int idx = tid; idx < 16 * TT; idx += 256) {
        int o = g * 16 + idx / TT;
        out[base + idx] = (yp[idx] - mu) * rstd * gw[o] + gb[o];
    }
}

extern "C" void kernel_launch(void* const* d_in, const int* in_sizes, int n_in,
                              void* d_out, int out_size) {
    const float* x     = (const float*)d_in[0];
    const float* qkv_w = (const float*)d_in[1];
    const float* qkv_b = (const float*)d_in[2];
    const float* rh_k  = (const float*)d_in[3];
    const float* rw_k  = (const float*)d_in[4];
    const float* rh_v  = (const float*)d_in[5];
    const float* rw_v  = (const float*)d_in[6];
    const float* fc_w  = (const float*)d_in[7];
    const float* fc_b  = (const float*)d_in[8];
    const float* gn_w  = (const float*)d_in[9];
    const float* gn_b  = (const float*)d_in[10];
    float* out = (float*)d_out;

    cudaFuncSetAttribute(k3_attn, cudaFuncAttributeMaxDynamicSharedMemorySize, 102912);

    k0_prep<<<607, 256>>>(rh_v, rw_v, rh_k, rw_k, qkv_w, fc_w);
    k1_qkv<<<dim3(9, 12, BB), 256>>>(x, qkv_b);
    kE_gemm<<<dim3(9, 128), 256>>>();
    k3_attn<<<dim3(36, BB), 256, 102912>>>();
    k4_fc<<<dim3(9, 4, BB), 256>>>(x, fc_b);
    k56_gn<<<256, 256>>>(out, gn_w, gn_b);
}